// round 8
// baseline (speedup 1.0000x reference)
#include <cuda_runtime.h>
#include <cuda_bf16.h>

// Problem dims (fixed by the reference)
#define BB   8
#define NN   1024
#define DD   256
#define HH   512
#define MMd  256
#define OOd  256
#define ROWS (BB*NN)          // 8192

// ---------------------------------------------------------------------------
// Scratch (device globals — allocation-free per harness rules)
// ---------------------------------------------------------------------------
__device__ float g_xproj[(size_t)ROWS * 4 * HH];       // 64 MB
__device__ float g_h    [(size_t)ROWS * HH];           // 16 MB
__device__ float g_scores[(size_t)BB * NN * NN];       // 32 MB (w in-place)
__device__ float g_sagg [(size_t)ROWS * HH];           // 16 MB
__device__ float g_t1   [(size_t)2 * ROWS * MMd];      // 16 MB (batched hidden)
__device__ float g_axav [(size_t)2 * ROWS * MMd];      // 16 MB (ax | av)
__device__ float g_agg  [(size_t)ROWS * OOd];          // 8 MB
__device__ float g_wp1  [(size_t)2 * MMd * HH];        // packed gx_W1|gv_W1
__device__ float g_wp2  [(size_t)2 * MMd * MMd];       // packed gx_W2|gv_W2
__device__ float g_bp1  [2 * MMd];
__device__ float g_bp2  [2 * MMd];
__device__ float g_rmask[ROWS];
__device__ unsigned g_cnt[NN];                         // per-timestep counters

__global__ void reset_cnt_kernel() {
    g_cnt[threadIdx.x] = 0u;
}

// ---------------------------------------------------------------------------
// f32x2 helpers (FFMA2 — only reachable via PTX fma.rn.f32x2)
// ---------------------------------------------------------------------------
__device__ __forceinline__ void ffma2(unsigned long long& d,
                                      unsigned long long a, unsigned long long b) {
    asm("fma.rn.f32x2 %0, %1, %2, %3;" : "=l"(d) : "l"(a), "l"(b), "l"(d));
}
__device__ __forceinline__ float2 up2(unsigned long long p) {
    unsigned lo, hi;
    asm("mov.b64 {%0, %1}, %2;" : "=r"(lo), "=r"(hi) : "l"(p));
    return make_float2(__uint_as_float(lo), __uint_as_float(hi));
}
__device__ __forceinline__ unsigned long long pk2(float a, float b) {
    unsigned long long r;
    asm("mov.b64 %0, {%1, %2};" : "=l"(r)
        : "r"(__float_as_uint(a)), "r"(__float_as_uint(b)));
    return r;
}

// ---------------------------------------------------------------------------
// Generic fp32 tiled GEMM, double-buffered smem + register staging, FFMA2
// microkernel. Tile 128x128x16, 256 threads, 8x8 microtile.
//   TRANSB=true : B is W [N,K] row-major; TRANSB=false: B is [K,N] row-major.
// ---------------------------------------------------------------------------
template<bool TRANSB, bool RELU, bool ACCUM, bool RMASK>
__global__ void __launch_bounds__(256) gemm_k(
    const float* __restrict__ A, const float* __restrict__ B,
    const float* __restrict__ bias, const float* __restrict__ rmask,
    float* __restrict__ C,
    int K, int lda, int ldb, int ldc,
    long long sA, long long sB, long long sC, long long sBias)
{
    __shared__ __align__(16) float As[2][16][132];
    __shared__ __align__(16) float Bs[2][16][132];

    const int bz = blockIdx.z;
    A += (long long)bz * sA;
    B += (long long)bz * sB;
    C += (long long)bz * sC;
    if (bias) bias += (long long)bz * sBias;

    const int m0 = blockIdx.y * 128;
    const int n0 = blockIdx.x * 128;
    const int tid = threadIdx.x;
    const int tx = tid & 15;   // -> n
    const int ty = tid >> 4;   // -> m

    // per-thread load coordinates (2 float4 per tile per array)
    const int f0 = tid,        f1 = tid + 256;
    const int r0 = f0 >> 2,    c0 = (f0 & 3) << 2;   // A / B-transposed layout
    const int r1 = f1 >> 2,    c1 = (f1 & 3) << 2;
    const int kr0 = f0 >> 5,   nc0 = (f0 & 31) << 2; // B non-transposed layout
    const int kr1 = f1 >> 5,   nc1 = (f1 & 31) << 2;

    float4 ra0, ra1, rb0, rb1;

    auto LD = [&](int k0) {
        ra0 = *(const float4*)(A + (long long)(m0 + r0) * lda + k0 + c0);
        ra1 = *(const float4*)(A + (long long)(m0 + r1) * lda + k0 + c1);
        if (TRANSB) {
            rb0 = *(const float4*)(B + (long long)(n0 + r0) * ldb + k0 + c0);
            rb1 = *(const float4*)(B + (long long)(n0 + r1) * ldb + k0 + c1);
        } else {
            rb0 = *(const float4*)(B + (long long)(k0 + kr0) * ldb + n0 + nc0);
            rb1 = *(const float4*)(B + (long long)(k0 + kr1) * ldb + n0 + nc1);
        }
    };
    auto STS = [&](int s) {
        As[s][c0 + 0][r0] = ra0.x; As[s][c0 + 1][r0] = ra0.y;
        As[s][c0 + 2][r0] = ra0.z; As[s][c0 + 3][r0] = ra0.w;
        As[s][c1 + 0][r1] = ra1.x; As[s][c1 + 1][r1] = ra1.y;
        As[s][c1 + 2][r1] = ra1.z; As[s][c1 + 3][r1] = ra1.w;
        if (TRANSB) {
            Bs[s][c0 + 0][r0] = rb0.x; Bs[s][c0 + 1][r0] = rb0.y;
            Bs[s][c0 + 2][r0] = rb0.z; Bs[s][c0 + 3][r0] = rb0.w;
            Bs[s][c1 + 0][r1] = rb1.x; Bs[s][c1 + 1][r1] = rb1.y;
            Bs[s][c1 + 2][r1] = rb1.z; Bs[s][c1 + 3][r1] = rb1.w;
        } else {
            *(float4*)&Bs[s][kr0][nc0] = rb0;
            *(float4*)&Bs[s][kr1][nc1] = rb1;
        }
    };

    unsigned long long acc2[8][4];
#pragma unroll
    for (int i = 0; i < 8; i++)
#pragma unroll
        for (int j = 0; j < 4; j++) acc2[i][j] = 0ull;

    const int nt = K >> 4;
    LD(0);
    STS(0);
    __syncthreads();

    for (int t = 0; t < nt; t++) {
        const int cur = t & 1;
        if (t + 1 < nt) LD((t + 1) << 4);   // LDG hidden behind compute

#pragma unroll
        for (int kk = 0; kk < 16; kk++) {
            float a[8];
            *(float4*)&a[0] = *(const float4*)&As[cur][kk][ty * 8];
            *(float4*)&a[4] = *(const float4*)&As[cur][kk][ty * 8 + 4];
            ulonglong2 b01 = *(const ulonglong2*)&Bs[cur][kk][tx * 8];
            ulonglong2 b23 = *(const ulonglong2*)&Bs[cur][kk][tx * 8 + 4];
#pragma unroll
            for (int i = 0; i < 8; i++) {
                unsigned long long ap = pk2(a[i], a[i]);
                ffma2(acc2[i][0], ap, b01.x);
                ffma2(acc2[i][1], ap, b01.y);
                ffma2(acc2[i][2], ap, b23.x);
                ffma2(acc2[i][3], ap, b23.y);
            }
        }
        if (t + 1 < nt) {
            STS(cur ^ 1);
            __syncthreads();
        }
    }

    // ---- epilogue ----
#pragma unroll
    for (int i = 0; i < 8; i++) {
        int row = m0 + ty * 8 + i;
        float rm = 1.f;
        if (RMASK) rm = rmask[row];
#pragma unroll
        for (int jv = 0; jv < 2; jv++) {
            int col = n0 + tx * 8 + jv * 4;
            float2 p0 = up2(acc2[i][jv * 2 + 0]);
            float2 p1 = up2(acc2[i][jv * 2 + 1]);
            float4 v = make_float4(p0.x, p0.y, p1.x, p1.y);
            if (bias) {
                float4 bb = *(const float4*)(bias + col);
                v.x += bb.x; v.y += bb.y; v.z += bb.z; v.w += bb.w;
            }
            float4* cp = (float4*)(C + (long long)row * ldc + col);
            if (ACCUM) {
                float4 c0v = *cp;
                v.x += c0v.x; v.y += c0v.y; v.z += c0v.z; v.w += c0v.w;
            }
            if (RELU) {
                v.x = fmaxf(v.x, 0.f); v.y = fmaxf(v.y, 0.f);
                v.z = fmaxf(v.z, 0.f); v.w = fmaxf(v.w, 0.f);
            }
            if (RMASK) { v.x *= rm; v.y *= rm; v.z *= rm; v.w *= rm; }
            *cp = v;
        }
    }
}

// ---------------------------------------------------------------------------
// Persistent LSTM kernel: 128 CTAs x 256 threads.
// CTA k owns hidden units j0=4k..4k+3 (16 gate rows). W_hh slice lives in
// REGISTERS (each thread: 4 rows x 16 k-floats as 16x ulonglong2, FFMA2-ready).
// Warp w (rg=w>>1, bg=w&1) computes gate rows rg*4..+3 for batches bg*4..+3.
// Cross-CTA sync: per-step counter; all threads poll ld.acquire, tid0 does
// red.release after the h(t) store is block-visible.
// ---------------------------------------------------------------------------
#define LSTM_CTAS 128

__global__ void __launch_bounds__(256) lstm_kernel(
    const float* __restrict__ xproj,   // [8192, 2048] (no bias)
    const float* __restrict__ W_hh,    // [2048, 512]
    const float* __restrict__ b_ih,    // [2048]
    const float* __restrict__ b_hh,    // [2048]
    float* __restrict__ h_out)         // [8192, 512], row = b*1024 + t
{
    __shared__ __align__(16) float hsm[8 * 512];
    __shared__ float gsm[128];
    __shared__ float bsm[16];
    __shared__ float csm[32];

    const int tid  = threadIdx.x;
    const int cta  = blockIdx.x;
    const int j0   = cta * 4;
    const int w    = tid >> 5;
    const int lane = tid & 31;
    const int rg   = w >> 1;           // row group: rows rg*4 .. rg*4+3
    const int bg   = w & 1;            // batch group: batches bg*4 .. bg*4+3
    const int ub   = tid >> 2;         // update: batch
    const int ujj  = tid & 3;          // update: local hidden unit

    // W_hh slice into registers (pre-paired for FFMA2).
    ulonglong2 wq[4][4];
#pragma unroll
    for (int rr = 0; rr < 4; rr++) {
        int d = rg * 4 + rr;           // d = q*4 + jj
        int q = d >> 2, jj = d & 3;
        const float* src = W_hh + (long long)(q * 512 + j0 + jj) * 512;
#pragma unroll
        for (int i = 0; i < 4; i++)
            wq[rr][i] = *(const ulonglong2*)&src[lane * 4 + i * 128];
    }
    if (tid < 16) {
        int q = tid >> 2, jj = tid & 3;
        int r = q * 512 + j0 + jj;
        bsm[tid] = b_ih[r] + b_hh[r];
    }
    if (tid < 32) csm[tid] = 0.f;
    for (int idx = tid; idx < 8 * 512; idx += 256) hsm[idx] = 0.f;  // h(-1)=0
    __syncthreads();

    const float* Hbase = &hsm[bg * 4 * 512];

    for (int t = 0; t < 1024; t++) {
        // Prefetch x-projection (independent of the counter — overlaps the wait)
        float xp0 = 0.f, xp1 = 0.f, xp2 = 0.f, xp3 = 0.f;
        if (tid < 32) {
            long long base = (long long)(ub * 1024 + t) * 2048 + j0 + ujj;
            xp0 = __ldg(&xproj[base + 0 * 512]);
            xp1 = __ldg(&xproj[base + 1 * 512]);
            xp2 = __ldg(&xproj[base + 2 * 512]);
            xp3 = __ldg(&xproj[base + 3 * 512]);
        }
        // Wait for h(t-1) from all CTAs (every thread polls; pairs with release)
        if (t > 0) {
            const unsigned* cp = &g_cnt[t - 1];
            unsigned v;
            do {
                asm volatile("ld.acquire.gpu.u32 %0, [%1];"
                             : "=r"(v) : "l"(cp) : "memory");
            } while (v < (unsigned)LSTM_CTAS);
            // Stage h(t-1) into SMEM
#pragma unroll
            for (int ii = 0; ii < 4; ii++) {
                int f  = tid + ii * 256;
                int b  = f >> 7;
                int kk = (f & 127) * 4;
                *(float4*)&hsm[b * 512 + kk] =
                    *(const float4*)&h_out[(long long)(b * 1024 + t - 1) * 512 + kk];
            }
        }
        __syncthreads();

        // gates(d, b) = sum_k W[d][k] * h[b][k]   (4 rows x 4 batches / warp)
        unsigned long long acc[4][4];
#pragma unroll
        for (int rr = 0; rr < 4; rr++)
#pragma unroll
            for (int bb = 0; bb < 4; bb++) acc[rr][bb] = 0ull;

#pragma unroll
        for (int i = 0; i < 4; i++) {
            int kk = lane * 4 + i * 128;
            ulonglong2 hq[4];
#pragma unroll
            for (int bb = 0; bb < 4; bb++)
                hq[bb] = *(const ulonglong2*)&Hbase[bb * 512 + kk];
#pragma unroll
            for (int rr = 0; rr < 4; rr++)
#pragma unroll
                for (int bb = 0; bb < 4; bb++) {
                    ffma2(acc[rr][bb], wq[rr][i].x, hq[bb].x);
                    ffma2(acc[rr][bb], wq[rr][i].y, hq[bb].y);
                }
        }

        float val[4][4];
#pragma unroll
        for (int rr = 0; rr < 4; rr++)
#pragma unroll
            for (int bb = 0; bb < 4; bb++) {
                float2 p = up2(acc[rr][bb]);
                val[rr][bb] = p.x + p.y;
            }
#pragma unroll
        for (int off = 16; off > 0; off >>= 1)
#pragma unroll
            for (int rr = 0; rr < 4; rr++)
#pragma unroll
                for (int bb = 0; bb < 4; bb++)
                    val[rr][bb] += __shfl_xor_sync(0xffffffffu, val[rr][bb], off);
        if (lane == 0) {
#pragma unroll
            for (int rr = 0; rr < 4; rr++)
#pragma unroll
                for (int bb = 0; bb < 4; bb++)
                    gsm[(rg * 4 + rr) * 8 + bg * 4 + bb] = val[rr][bb];
        }
        __syncthreads();

        // Cell update (gate order i,f,g,o); fast sigmoid/tanh via MUFU
        if (tid < 32) {
            float gi = gsm[(0 * 4 + ujj) * 8 + ub] + xp0 + bsm[0 * 4 + ujj];
            float gf = gsm[(1 * 4 + ujj) * 8 + ub] + xp1 + bsm[1 * 4 + ujj];
            float gg = gsm[(2 * 4 + ujj) * 8 + ub] + xp2 + bsm[2 * 4 + ujj];
            float go = gsm[(3 * 4 + ujj) * 8 + ub] + xp3 + bsm[3 * 4 + ujj];
            float si = __fdividef(1.f, 1.f + __expf(-gi));
            float sf = __fdividef(1.f, 1.f + __expf(-gf));
            float so = __fdividef(1.f, 1.f + __expf(-go));
            float tg = 2.f * __fdividef(1.f, 1.f + __expf(-2.f * gg)) - 1.f;
            float c  = sf * csm[tid] + si * tg;
            csm[tid] = c;
            float tc = 2.f * __fdividef(1.f, 1.f + __expf(-2.f * c)) - 1.f;
            float h  = so * tc;
            h_out[(long long)(ub * 1024 + t) * 512 + j0 + ujj] = h;
        }
        __syncthreads();   // HB: h writes -> tid0's release below

        if (tid == 0) {
            const unsigned* cp = &g_cnt[t];
            asm volatile("red.release.gpu.add.u32 [%0], %1;"
                         :: "l"(cp), "r"(1u) : "memory");
        }
    }
}

// ---------------------------------------------------------------------------
// Masked softmax over scores rows; writes w in-place and the has-neighbor mask
// ---------------------------------------------------------------------------
__global__ void __launch_bounds__(256) softmax_kernel(
    float* __restrict__ scores, const int* __restrict__ adj,
    float* __restrict__ rmask)
{
    const int r = blockIdx.x;              // 0..8191 == (b*1024 + i)
    const int i = r & (NN - 1);
    float* srow      = scores + (long long)r * NN;
    const int* arow  = adj    + (long long)r * NN;
    const int tid  = threadIdx.x;
    const int lane = tid & 31, wid = tid >> 5;

    float s[4]; int m[4];
    float mx = -1e30f;
    int cnt = 0;
#pragma unroll
    for (int u = 0; u < 4; u++) {
        int j = tid + u * 256;
        float v  = srow[j];
        int   mk = (arow[j] > 0) && (j != i);
        s[u] = v; m[u] = mk;
        if (mk) { mx = fmaxf(mx, v); cnt++; }
    }

    __shared__ float rf[8];
    __shared__ int   ri[8];
    __shared__ float s_mx, s_inv;
    __shared__ int   s_cnt;

#pragma unroll
    for (int off = 16; off; off >>= 1) {
        mx   = fmaxf(mx, __shfl_xor_sync(0xffffffffu, mx, off));
        cnt += __shfl_xor_sync(0xffffffffu, cnt, off);
    }
    if (lane == 0) { rf[wid] = mx; ri[wid] = cnt; }
    __syncthreads();
    if (tid == 0) {
        float m2 = rf[0]; int c2 = ri[0];
        for (int k = 1; k < 8; k++) { m2 = fmaxf(m2, rf[k]); c2 += ri[k]; }
        s_mx = m2; s_cnt = c2;
    }
    __syncthreads();

    if (s_cnt == 0) {
#pragma unroll
        for (int u = 0; u < 4; u++) srow[tid + u * 256] = 0.f;
        if (tid == 0) rmask[r] = 0.f;
        return;
    }
    float mxAll = s_mx;
    float e[4];
    float sum = 0.f;
#pragma unroll
    for (int u = 0; u < 4; u++) {
        e[u] = m[u] ? expf(s[u] - mxAll) : 0.f;
        sum += e[u];
    }
#pragma unroll
    for (int off = 16; off; off >>= 1) sum += __shfl_xor_sync(0xffffffffu, sum, off);
    if (lane == 0) rf[wid] = sum;
    __syncthreads();
    if (tid == 0) {
        float tot = 0.f;
        for (int k = 0; k < 8; k++) tot += rf[k];
        s_inv = 1.f / tot;
    }
    __syncthreads();
    float inv = s_inv;
#pragma unroll
    for (int u = 0; u < 4; u++) srow[tid + u * 256] = e[u] * inv;
    if (tid == 0) rmask[r] = 1.f;
}

// ---------------------------------------------------------------------------
// Launch
// ---------------------------------------------------------------------------
extern "C" void kernel_launch(void* const* d_in, const int* in_sizes, int n_in,
                              void* d_out, int out_size)
{
    const float* feats = (const float*)d_in[0];
    const int*   adj   = (const int*)  d_in[1];
    const float* W_ih  = (const float*)d_in[2];
    const float* W_hh  = (const float*)d_in[3];
    const float* b_ih  = (const float*)d_in[4];
    const float* b_hh  = (const float*)d_in[5];
    const float* gx_W1 = (const float*)d_in[6];
    const float* gx_b1 = (const float*)d_in[7];
    const float* gx_W2 = (const float*)d_in[8];
    const float* gx_b2 = (const float*)d_in[9];
    const float* gz_W1 = (const float*)d_in[10];
    const float* gz_b1 = (const float*)d_in[11];
    const float* gz_W2 = (const float*)d_in[12];
    const float* gz_b2 = (const float*)d_in[13];
    const float* gv_W1 = (const float*)d_in[14];
    const float* gv_b1 = (const float*)d_in[15];
    const float* gv_W2 = (const float*)d_in[16];
    const float* gv_b2 = (const float*)d_in[17];
    const float* gn_W1 = (const float*)d_in[18];
    const float* gn_b1 = (const float*)d_in[19];
    const float* gn_W2 = (const float*)d_in[20];
    const float* gn_b2 = (const float*)d_in[21];
    const float* out_W = (const float*)d_in[22];
    const float* out_b = (const float*)d_in[23];
    float* out = (float*)d_out;

    float *xproj, *h, *scores, *sagg, *t1, *axav, *agg, *rmask;
    float *wp1, *wp2, *bp1, *bp2;
    cudaGetSymbolAddress((void**)&xproj,  g_xproj);
    cudaGetSymbolAddress((void**)&h,      g_h);
    cudaGetSymbolAddress((void**)&scores, g_scores);
    cudaGetSymbolAddress((void**)&sagg,   g_sagg);
    cudaGetSymbolAddress((void**)&t1,     g_t1);
    cudaGetSymbolAddress((void**)&axav,   g_axav);
    cudaGetSymbolAddress((void**)&agg,    g_agg);
    cudaGetSymbolAddress((void**)&rmask,  g_rmask);
    cudaGetSymbolAddress((void**)&wp1,    g_wp1);
    cudaGetSymbolAddress((void**)&wp2,    g_wp2);
    cudaGetSymbolAddress((void**)&bp1,    g_bp1);
    cudaGetSymbolAddress((void**)&bp2,    g_bp2);

    const long long PW1 = (long long)MMd * HH;    // 131072
    const long long PW2 = (long long)MMd * MMd;   // 65536
    const long long PT  = (long long)ROWS * MMd;  // 2097152
    float* ax = axav;
    float* av = axav + PT;

    // Pack gx|gv weights/biases for batched MLP GEMMs (tiny D2D copies)
    cudaMemcpyAsync(wp1,       gx_W1, PW1 * 4, cudaMemcpyDeviceToDevice);
    cudaMemcpyAsync(wp1 + PW1, gv_W1, PW1 * 4, cudaMemcpyDeviceToDevice);
    cudaMemcpyAsync(wp2,       gx_W2, PW2 * 4, cudaMemcpyDeviceToDevice);
    cudaMemcpyAsync(wp2 + PW2, gv_W2, PW2 * 4, cudaMemcpyDeviceToDevice);
    cudaMemcpyAsync(bp1,       gx_b1, MMd * 4, cudaMemcpyDeviceToDevice);
    cudaMemcpyAsync(bp1 + MMd, gv_b1, MMd * 4, cudaMemcpyDeviceToDevice);
    cudaMemcpyAsync(bp2,       gx_b2, MMd * 4, cudaMemcpyDeviceToDevice);
    cudaMemcpyAsync(bp2 + MMd, gv_b2, MMd * 4, cudaMemcpyDeviceToDevice);

    const dim3 blk(256);
    const dim3 gSmall(2, 64, 1);   // [8192 x 256] outputs

    // 1. xproj = feats @ W_ih^T            [8192,2048], K=256
    gemm_k<true,false,false,false><<<dim3(16, 64, 1), blk>>>(
        feats, W_ih, nullptr, nullptr, xproj, 256, 256, 256, 2048, 0, 0, 0, 0);

    // 2. LSTM recurrence -> h [8192,512]
    reset_cnt_kernel<<<1, NN>>>();
    lstm_kernel<<<LSTM_CTAS, 256>>>(xproj, W_hh, b_ih, b_hh, h);

    // 3+4. batched gx/gv MLPs: t1[z] = relu(h @ W1[z]^T + b1[z]);
    //      axav[z] = t1[z] @ W2[z]^T + b2[z]
    gemm_k<true,true,false,false><<<dim3(2, 64, 2), blk>>>(
        h, wp1, bp1, nullptr, t1, 512, 512, 512, 256, 0, PW1, PT, MMd);
    gemm_k<true,false,false,false><<<dim3(2, 64, 2), blk>>>(
        t1, wp2, bp2, nullptr, axav, 256, 256, 256, 256, PT, PW2, PT, MMd);

    // 5. scores[b] = ax[b] @ av[b]^T       batched [1024,1024], K=256
    gemm_k<true,false,false,false><<<dim3(8, 8, 8), blk>>>(
        ax, av, nullptr, nullptr, scores, 256, 256, 256, 1024,
        (long long)1024 * 256, (long long)1024 * 256, (long long)1024 * 1024, 0);

    // 6. w = masked softmax(scores) (in place) + rmask
    softmax_kernel<<<ROWS, 256>>>(scores, adj, rmask);

    // 7. sagg[b] = w[b] @ h[b]             batched [1024,512], K=1024
    gemm_k<false,false,false,false><<<dim3(4, 8, 8), blk>>>(
        scores, h, nullptr, nullptr, sagg, 1024, 1024, 512, 512,
        (long long)1024 * 1024, (long long)1024 * 512, (long long)1024 * 512, 0);

    // 8. z = mlp_gz(sagg)    (t1 slot0 -> axav slot0; both free now)
    gemm_k<true,true,false,false><<<gSmall, blk>>>(
        sagg, gz_W1, gz_b1, nullptr, t1, 512, 512, 512, 256, 0, 0, 0, 0);
    gemm_k<true,false,false,false><<<gSmall, blk>>>(
        t1, gz_W2, gz_b2, nullptr, axav, 256, 256, 256, 256, 0, 0, 0, 0);

    // 9. agg = mlp_gn(z) * has_nb
    gemm_k<true,true,false,false><<<gSmall, blk>>>(
        axav, gn_W1, gn_b1, nullptr, t1, 256, 256, 256, 256, 0, 0, 0, 0);
    gemm_k<true,false,false,true><<<gSmall, blk>>>(
        t1, gn_W2, gn_b2, rmask, agg, 256, 256, 256, 256, 0, 0, 0, 0);

    // 10. out = h @ out_W[:, :512]^T + out_b ;  out += agg @ out_W[:, 512:]^T
    gemm_k<true,false,false,false><<<gSmall, blk>>>(
        h, out_W, out_b, nullptr, out, 512, 512, 768, 256, 0, 0, 0, 0);
    gemm_k<true,false,true,false><<<gSmall, blk>>>(
        agg, out_W + 512, nullptr, nullptr, out, 256, 256, 768, 256, 0, 0, 0, 0);
}

// round 13
// speedup vs baseline: 1.1880x; 1.1880x over previous
#include <cuda_runtime.h>
#include <cuda_bf16.h>

// Problem dims (fixed by the reference)
#define BB   8
#define NN   1024
#define DD   256
#define HH   512
#define MMd  256
#define OOd  256
#define ROWS (BB*NN)          // 8192

// ---------------------------------------------------------------------------
// Scratch (device globals — allocation-free per harness rules)
// ---------------------------------------------------------------------------
__device__ float g_xproj[(size_t)ROWS * 4 * HH];       // 64 MB
__device__ float g_h    [(size_t)ROWS * HH];           // 16 MB
__device__ float g_scores[(size_t)BB * NN * NN];       // 32 MB (w in-place)
__device__ float g_sagg [(size_t)ROWS * HH];           // 16 MB
__device__ float g_t1   [(size_t)2 * ROWS * MMd];      // 16 MB (batched hidden)
__device__ float g_axav [(size_t)2 * ROWS * MMd];      // 16 MB (ax | av)
__device__ float g_agg  [(size_t)ROWS * OOd];          // 8 MB
__device__ float g_wp1  [(size_t)2 * MMd * HH];        // packed gx_W1|gv_W1
__device__ float g_wp2  [(size_t)2 * MMd * MMd];       // packed gx_W2|gv_W2
__device__ float g_bp1  [2 * MMd];
__device__ float g_bp2  [2 * MMd];
__device__ float g_rmask[ROWS];
__device__ unsigned g_cnt[NN];                         // per-timestep counters

__global__ void reset_cnt_kernel() {
    g_cnt[threadIdx.x] = 0u;
}

// ---------------------------------------------------------------------------
// f32x2 helpers (FFMA2 — only reachable via PTX fma.rn.f32x2)
// ---------------------------------------------------------------------------
__device__ __forceinline__ void ffma2(unsigned long long& d,
                                      unsigned long long a, unsigned long long b) {
    asm("fma.rn.f32x2 %0, %1, %2, %3;" : "=l"(d) : "l"(a), "l"(b), "l"(d));
}
__device__ __forceinline__ float2 up2(unsigned long long p) {
    unsigned lo, hi;
    asm("mov.b64 {%0, %1}, %2;" : "=r"(lo), "=r"(hi) : "l"(p));
    return make_float2(__uint_as_float(lo), __uint_as_float(hi));
}
__device__ __forceinline__ unsigned long long pk2(float a, float b) {
    unsigned long long r;
    asm("mov.b64 %0, {%1, %2};" : "=l"(r)
        : "r"(__float_as_uint(a)), "r"(__float_as_uint(b)));
    return r;
}

// ---------------------------------------------------------------------------
// Generic fp32 tiled GEMM (R7 single-buffer version — 2 CTAs/SM), FFMA2
// microkernel. Tile 128x128x16, 256 threads, 8x8 microtile.
//   TRANSB=true : B is W [N,K] row-major; TRANSB=false: B is [K,N] row-major.
// ---------------------------------------------------------------------------
template<bool TRANSB, bool RELU, bool ACCUM, bool RMASK>
__global__ void __launch_bounds__(256, 2) gemm_k(
    const float* __restrict__ A, const float* __restrict__ B,
    const float* __restrict__ bias, const float* __restrict__ rmask,
    float* __restrict__ C,
    int K, int lda, int ldb, int ldc,
    long long sA, long long sB, long long sC, long long sBias)
{
    __shared__ __align__(16) float As[16][132];
    __shared__ __align__(16) float Bs[16][132];

    const int bz = blockIdx.z;
    A += (long long)bz * sA;
    B += (long long)bz * sB;
    C += (long long)bz * sC;
    if (bias) bias += (long long)bz * sBias;

    const int m0 = blockIdx.y * 128;
    const int n0 = blockIdx.x * 128;
    const int tid = threadIdx.x;
    const int tx = tid & 15;   // -> n
    const int ty = tid >> 4;   // -> m

    unsigned long long acc2[8][4];
#pragma unroll
    for (int i = 0; i < 8; i++)
#pragma unroll
        for (int j = 0; j < 4; j++) acc2[i][j] = 0ull;

    for (int k0 = 0; k0 < K; k0 += 16) {
        // ---- load A tile (transpose into As[k][m]) ----
#pragma unroll
        for (int ii = 0; ii < 2; ii++) {
            int f   = tid + ii * 256;
            int row = f >> 2;
            int cg  = (f & 3) << 2;
            float4 v = *(const float4*)(A + (long long)(m0 + row) * lda + k0 + cg);
            As[cg + 0][row] = v.x;
            As[cg + 1][row] = v.y;
            As[cg + 2][row] = v.z;
            As[cg + 3][row] = v.w;
        }
        // ---- load B tile ----
        if (TRANSB) {
#pragma unroll
            for (int ii = 0; ii < 2; ii++) {
                int f   = tid + ii * 256;
                int row = f >> 2;              // n index
                int cg  = (f & 3) << 2;        // k index
                float4 v = *(const float4*)(B + (long long)(n0 + row) * ldb + k0 + cg);
                Bs[cg + 0][row] = v.x;
                Bs[cg + 1][row] = v.y;
                Bs[cg + 2][row] = v.z;
                Bs[cg + 3][row] = v.w;
            }
        } else {
#pragma unroll
            for (int ii = 0; ii < 2; ii++) {
                int f  = tid + ii * 256;
                int kr = f >> 5;
                int nc = (f & 31) << 2;
                *(float4*)&Bs[kr][nc] =
                    *(const float4*)(B + (long long)(k0 + kr) * ldb + n0 + nc);
            }
        }
        __syncthreads();

#pragma unroll
        for (int kk = 0; kk < 16; kk++) {
            float a[8];
            *(float4*)&a[0] = *(const float4*)&As[kk][ty * 8];
            *(float4*)&a[4] = *(const float4*)&As[kk][ty * 8 + 4];
            ulonglong2 b01 = *(const ulonglong2*)&Bs[kk][tx * 8];
            ulonglong2 b23 = *(const ulonglong2*)&Bs[kk][tx * 8 + 4];
#pragma unroll
            for (int i = 0; i < 8; i++) {
                unsigned long long ap = pk2(a[i], a[i]);
                ffma2(acc2[i][0], ap, b01.x);
                ffma2(acc2[i][1], ap, b01.y);
                ffma2(acc2[i][2], ap, b23.x);
                ffma2(acc2[i][3], ap, b23.y);
            }
        }
        __syncthreads();
    }

    // ---- epilogue ----
#pragma unroll
    for (int i = 0; i < 8; i++) {
        int row = m0 + ty * 8 + i;
        float rm = 1.f;
        if (RMASK) rm = rmask[row];
#pragma unroll
        for (int jv = 0; jv < 2; jv++) {
            int col = n0 + tx * 8 + jv * 4;
            float2 p0 = up2(acc2[i][jv * 2 + 0]);
            float2 p1 = up2(acc2[i][jv * 2 + 1]);
            float4 v = make_float4(p0.x, p0.y, p1.x, p1.y);
            if (bias) {
                float4 bb = *(const float4*)(bias + col);
                v.x += bb.x; v.y += bb.y; v.z += bb.z; v.w += bb.w;
            }
            float4* cp = (float4*)(C + (long long)row * ldc + col);
            if (ACCUM) {
                float4 c0v = *cp;
                v.x += c0v.x; v.y += c0v.y; v.z += c0v.z; v.w += c0v.w;
            }
            if (RELU) {
                v.x = fmaxf(v.x, 0.f); v.y = fmaxf(v.y, 0.f);
                v.z = fmaxf(v.z, 0.f); v.w = fmaxf(v.w, 0.f);
            }
            if (RMASK) { v.x *= rm; v.y *= rm; v.z *= rm; v.w *= rm; }
            *cp = v;
        }
    }
}

// ---------------------------------------------------------------------------
// Persistent LSTM kernel: 128 CTAs x 256 threads.
// CTA k owns hidden units j0=4k..4k+3. Warp (u, bg) = (w>>1, w&1) owns the
// FOUR GATE ROWS of hidden unit j0+u (rows q*512+j0+u, q=0..3 in W_hh) for
// batches bg*4..bg*4+3. After a full butterfly reduce every lane holds all
// 16 (gate,batch) sums, so lanes 0-3 do the complete cell update in-warp
// (c in registers, no gate staging through smem, no separate update phase).
// W_hh slice lives in registers (FFMA2-prepacked). Cross-CTA sync: per-step
// counter; tid0 polls ld.acquire / fires red.release.
// ---------------------------------------------------------------------------
#define LSTM_CTAS 128

__global__ void __launch_bounds__(256) lstm_kernel(
    const float* __restrict__ xproj,   // [8192, 2048] (no bias)
    const float* __restrict__ W_hh,    // [2048, 512]
    const float* __restrict__ b_ih,    // [2048]
    const float* __restrict__ b_hh,    // [2048]
    float* __restrict__ h_out)         // [8192, 512], row = b*1024 + t
{
    __shared__ __align__(16) float hsm[8 * 512];

    const int tid  = threadIdx.x;
    const int cta  = blockIdx.x;
    const int j0   = cta * 4;
    const int w    = tid >> 5;
    const int lane = tid & 31;
    const int u    = w >> 1;           // hidden unit j0+u
    const int bg   = w & 1;            // batch group: batches bg*4 .. bg*4+3

    // W_hh rows q*512 + j0 + u (q = gate i,f,g,o) into registers, FFMA2-paired
    ulonglong2 wq[4][4];
    float bq[4];
#pragma unroll
    for (int q = 0; q < 4; q++) {
        int r = q * 512 + j0 + u;
        const float* src = W_hh + (long long)r * 512;
#pragma unroll
        for (int i = 0; i < 4; i++)
            wq[q][i] = *(const ulonglong2*)&src[lane * 4 + i * 128];
        bq[q] = b_ih[r] + b_hh[r];
    }
    float c = 0.f;                     // valid on lanes 0-3: batch bg*4+lane

    for (int idx = tid; idx < 8 * 512; idx += 256) hsm[idx] = 0.f;  // h(-1)=0
    __syncthreads();

    const float* Hbase = &hsm[bg * 4 * 512];

    for (int t = 0; t < 1024; t++) {
        // Prefetch x-projection for the update lanes (overlaps the wait)
        float xp[4] = {0.f, 0.f, 0.f, 0.f};
        if (lane < 4) {
            int batch = bg * 4 + lane;
            long long base = (long long)(batch * 1024 + t) * 2048 + j0 + u;
#pragma unroll
            for (int q = 0; q < 4; q++)
                xp[q] = __ldg(&xproj[base + q * 512]);
        }
        if (t > 0) {
            // Wait for h(t-1) from all CTAs (tid0 polls; pairs with release)
            if (tid == 0) {
                const unsigned* cp = &g_cnt[t - 1];
                unsigned v;
                do {
                    asm volatile("ld.acquire.gpu.u32 %0, [%1];"
                                 : "=r"(v) : "l"(cp) : "memory");
                } while (v < (unsigned)LSTM_CTAS);
            }
            __syncthreads();
            // Stage h(t-1) into SMEM
#pragma unroll
            for (int ii = 0; ii < 4; ii++) {
                int f  = tid + ii * 256;
                int b  = f >> 7;
                int kk = (f & 127) * 4;
                *(float4*)&hsm[b * 512 + kk] =
                    *(const float4*)&h_out[(long long)(b * 1024 + t - 1) * 512 + kk];
            }
            __syncthreads();
        }

        // gates(q, b) = sum_k W[q*512+j0+u][k] * h[b][k]
        unsigned long long acc[4][4];
#pragma unroll
        for (int q = 0; q < 4; q++)
#pragma unroll
            for (int bb = 0; bb < 4; bb++) acc[q][bb] = 0ull;

#pragma unroll
        for (int i = 0; i < 4; i++) {
            int kk = lane * 4 + i * 128;
            ulonglong2 hq[4];
#pragma unroll
            for (int bb = 0; bb < 4; bb++)
                hq[bb] = *(const ulonglong2*)&Hbase[bb * 512 + kk];
#pragma unroll
            for (int q = 0; q < 4; q++)
#pragma unroll
                for (int bb = 0; bb < 4; bb++) {
                    ffma2(acc[q][bb], wq[q][i].x, hq[bb].x);
                    ffma2(acc[q][bb], wq[q][i].y, hq[bb].y);
                }
        }

        float val[4][4];
#pragma unroll
        for (int q = 0; q < 4; q++)
#pragma unroll
            for (int bb = 0; bb < 4; bb++) {
                float2 p = up2(acc[q][bb]);
                val[q][bb] = p.x + p.y;
            }
#pragma unroll
        for (int off = 16; off > 0; off >>= 1)
#pragma unroll
            for (int q = 0; q < 4; q++)
#pragma unroll
                for (int bb = 0; bb < 4; bb++)
                    val[q][bb] += __shfl_xor_sync(0xffffffffu, val[q][bb], off);

        // In-warp cell update: lane bb handles batch bg*4+bb of unit j0+u
        if (lane < 4) {
            int batch = bg * 4 + lane;
            float gi = val[0][lane] + xp[0] + bq[0];
            float gf = val[1][lane] + xp[1] + bq[1];
            float gg = val[2][lane] + xp[2] + bq[2];
            float go = val[3][lane] + xp[3] + bq[3];
            float si = __fdividef(1.f, 1.f + __expf(-gi));
            float sf = __fdividef(1.f, 1.f + __expf(-gf));
            float so = __fdividef(1.f, 1.f + __expf(-go));
            float tg = 2.f * __fdividef(1.f, 1.f + __expf(-2.f * gg)) - 1.f;
            c = sf * c + si * tg;
            float tc = 2.f * __fdividef(1.f, 1.f + __expf(-2.f * c)) - 1.f;
            h_out[(long long)(batch * 1024 + t) * 512 + j0 + u] = so * tc;
        }
        __syncthreads();   // HB: all warps' h stores -> tid0's release

        if (tid == 0) {
            const unsigned* cp = &g_cnt[t];
            asm volatile("red.release.gpu.add.u32 [%0], %1;"
                         :: "l"(cp), "r"(1u) : "memory");
        }
    }
}

// ---------------------------------------------------------------------------
// Masked softmax over scores rows; writes w in-place and the has-neighbor mask
// ---------------------------------------------------------------------------
__global__ void __launch_bounds__(256) softmax_kernel(
    float* __restrict__ scores, const int* __restrict__ adj,
    float* __restrict__ rmask)
{
    const int r = blockIdx.x;              // 0..8191 == (b*1024 + i)
    const int i = r & (NN - 1);
    float* srow      = scores + (long long)r * NN;
    const int* arow  = adj    + (long long)r * NN;
    const int tid  = threadIdx.x;
    const int lane = tid & 31, wid = tid >> 5;

    float s[4]; int m[4];
    float mx = -1e30f;
    int cnt = 0;
#pragma unroll
    for (int u = 0; u < 4; u++) {
        int j = tid + u * 256;
        float v  = srow[j];
        int   mk = (arow[j] > 0) && (j != i);
        s[u] = v; m[u] = mk;
        if (mk) { mx = fmaxf(mx, v); cnt++; }
    }

    __shared__ float rf[8];
    __shared__ int   ri[8];
    __shared__ float s_mx, s_inv;
    __shared__ int   s_cnt;

#pragma unroll
    for (int off = 16; off; off >>= 1) {
        mx   = fmaxf(mx, __shfl_xor_sync(0xffffffffu, mx, off));
        cnt += __shfl_xor_sync(0xffffffffu, cnt, off);
    }
    if (lane == 0) { rf[wid] = mx; ri[wid] = cnt; }
    __syncthreads();
    if (tid == 0) {
        float m2 = rf[0]; int c2 = ri[0];
        for (int k = 1; k < 8; k++) { m2 = fmaxf(m2, rf[k]); c2 += ri[k]; }
        s_mx = m2; s_cnt = c2;
    }
    __syncthreads();

    if (s_cnt == 0) {
#pragma unroll
        for (int u = 0; u < 4; u++) srow[tid + u * 256] = 0.f;
        if (tid == 0) rmask[r] = 0.f;
        return;
    }
    float mxAll = s_mx;
    float e[4];
    float sum = 0.f;
#pragma unroll
    for (int u = 0; u < 4; u++) {
        e[u] = m[u] ? expf(s[u] - mxAll) : 0.f;
        sum += e[u];
    }
#pragma unroll
    for (int off = 16; off; off >>= 1) sum += __shfl_xor_sync(0xffffffffu, sum, off);
    if (lane == 0) rf[wid] = sum;
    __syncthreads();
    if (tid == 0) {
        float tot = 0.f;
        for (int k = 0; k < 8; k++) tot += rf[k];
        s_inv = 1.f / tot;
    }
    __syncthreads();
    float inv = s_inv;
#pragma unroll
    for (int u = 0; u < 4; u++) srow[tid + u * 256] = e[u] * inv;
    if (tid == 0) rmask[r] = 1.f;
}

// ---------------------------------------------------------------------------
// Launch
// ---------------------------------------------------------------------------
extern "C" void kernel_launch(void* const* d_in, const int* in_sizes, int n_in,
                              void* d_out, int out_size)
{
    const float* feats = (const float*)d_in[0];
    const int*   adj   = (const int*)  d_in[1];
    const float* W_ih  = (const float*)d_in[2];
    const float* W_hh  = (const float*)d_in[3];
    const float* b_ih  = (const float*)d_in[4];
    const float* b_hh  = (const float*)d_in[5];
    const float* gx_W1 = (const float*)d_in[6];
    const float* gx_b1 = (const float*)d_in[7];
    const float* gx_W2 = (const float*)d_in[8];
    const float* gx_b2 = (const float*)d_in[9];
    const float* gz_W1 = (const float*)d_in[10];
    const float* gz_b1 = (const float*)d_in[11];
    const float* gz_W2 = (const float*)d_in[12];
    const float* gz_b2 = (const float*)d_in[13];
    const float* gv_W1 = (const float*)d_in[14];
    const float* gv_b1 = (const float*)d_in[15];
    const float* gv_W2 = (const float*)d_in[16];
    const float* gv_b2 = (const float*)d_in[17];
    const float* gn_W1 = (const float*)d_in[18];
    const float* gn_b1 = (const float*)d_in[19];
    const float* gn_W2 = (const float*)d_in[20];
    const float* gn_b2 = (const float*)d_in[21];
    const float* out_W = (const float*)d_in[22];
    const float* out_b = (const float*)d_in[23];
    float* out = (float*)d_out;

    float *xproj, *h, *scores, *sagg, *t1, *axav, *agg, *rmask;
    float *wp1, *wp2, *bp1, *bp2;
    cudaGetSymbolAddress((void**)&xproj,  g_xproj);
    cudaGetSymbolAddress((void**)&h,      g_h);
    cudaGetSymbolAddress((void**)&scores, g_scores);
    cudaGetSymbolAddress((void**)&sagg,   g_sagg);
    cudaGetSymbolAddress((void**)&t1,     g_t1);
    cudaGetSymbolAddress((void**)&axav,   g_axav);
    cudaGetSymbolAddress((void**)&agg,    g_agg);
    cudaGetSymbolAddress((void**)&rmask,  g_rmask);
    cudaGetSymbolAddress((void**)&wp1,    g_wp1);
    cudaGetSymbolAddress((void**)&wp2,    g_wp2);
    cudaGetSymbolAddress((void**)&bp1,    g_bp1);
    cudaGetSymbolAddress((void**)&bp2,    g_bp2);

    const long long PW1 = (long long)MMd * HH;    // 131072
    const long long PW2 = (long long)MMd * MMd;   // 65536
    const long long PT  = (long long)ROWS * MMd;  // 2097152
    float* ax = axav;
    float* av = axav + PT;

    // Pack gx|gv weights/biases for batched MLP GEMMs (tiny D2D copies)
    cudaMemcpyAsync(wp1,       gx_W1, PW1 * 4, cudaMemcpyDeviceToDevice);
    cudaMemcpyAsync(wp1 + PW1, gv_W1, PW1 * 4, cudaMemcpyDeviceToDevice);
    cudaMemcpyAsync(wp2,       gx_W2, PW2 * 4, cudaMemcpyDeviceToDevice);
    cudaMemcpyAsync(wp2 + PW2, gv_W2, PW2 * 4, cudaMemcpyDeviceToDevice);
    cudaMemcpyAsync(bp1,       gx_b1, MMd * 4, cudaMemcpyDeviceToDevice);
    cudaMemcpyAsync(bp1 + MMd, gv_b1, MMd * 4, cudaMemcpyDeviceToDevice);
    cudaMemcpyAsync(bp2,       gx_b2, MMd * 4, cudaMemcpyDeviceToDevice);
    cudaMemcpyAsync(bp2 + MMd, gv_b2, MMd * 4, cudaMemcpyDeviceToDevice);

    const dim3 blk(256);
    const dim3 gSmall(2, 64, 1);   // [8192 x 256] outputs

    // 1. xproj = feats @ W_ih^T            [8192,2048], K=256
    gemm_k<true,false,false,false><<<dim3(16, 64, 1), blk>>>(
        feats, W_ih, nullptr, nullptr, xproj, 256, 256, 256, 2048, 0, 0, 0, 0);

    // 2. LSTM recurrence -> h [8192,512]
    reset_cnt_kernel<<<1, NN>>>();
    lstm_kernel<<<LSTM_CTAS, 256>>>(xproj, W_hh, b_ih, b_hh, h);

    // 3+4. batched gx/gv MLPs
    gemm_k<true,true,false,false><<<dim3(2, 64, 2), blk>>>(
        h, wp1, bp1, nullptr, t1, 512, 512, 512, 256, 0, PW1, PT, MMd);
    gemm_k<true,false,false,false><<<dim3(2, 64, 2), blk>>>(
        t1, wp2, bp2, nullptr, axav, 256, 256, 256, 256, PT, PW2, PT, MMd);

    // 5. scores[b] = ax[b] @ av[b]^T       batched [1024,1024], K=256
    gemm_k<true,false,false,false><<<dim3(8, 8, 8), blk>>>(
        ax, av, nullptr, nullptr, scores, 256, 256, 256, 1024,
        (long long)1024 * 256, (long long)1024 * 256, (long long)1024 * 1024, 0);

    // 6. w = masked softmax(scores) (in place) + rmask
    softmax_kernel<<<ROWS, 256>>>(scores, adj, rmask);

    // 7. sagg[b] = w[b] @ h[b]             batched [1024,512], K=1024
    gemm_k<false,false,false,false><<<dim3(4, 8, 8), blk>>>(
        scores, h, nullptr, nullptr, sagg, 1024, 1024, 512, 512,
        (long long)1024 * 1024, (long long)1024 * 512, (long long)1024 * 512, 0);

    // 8. z = mlp_gz(sagg)
    gemm_k<true,true,false,false><<<gSmall, blk>>>(
        sagg, gz_W1, gz_b1, nullptr, t1, 512, 512, 512, 256, 0, 0, 0, 0);
    gemm_k<true,false,false,false><<<gSmall, blk>>>(
        t1, gz_W2, gz_b2, nullptr, axav, 256, 256, 256, 256, 0, 0, 0, 0);

    // 9. agg = mlp_gn(z) * has_nb
    gemm_k<true,true,false,false><<<gSmall, blk>>>(
        axav, gn_W1, gn_b1, nullptr, t1, 256, 256, 256, 256, 0, 0, 0, 0);
    gemm_k<true,false,false,true><<<gSmall, blk>>>(
        t1, gn_W2, gn_b2, rmask, agg, 256, 256, 256, 256, 0, 0, 0, 0);

    // 10. out = h @ out_W[:, :512]^T + out_b ;  out += agg @ out_W[:, 512:]^T
    gemm_k<true,false,false,false><<<gSmall, blk>>>(
        h, out_W, out_b, nullptr, out, 512, 512, 768, 256, 0, 0, 0, 0);
    gemm_k<true,false,true,false><<<gSmall, blk>>>(
        agg, out_W + 512, nullptr, nullptr, out, 256, 256, 768, 256, 0, 0, 0, 0);
}

// round 14
// speedup vs baseline: 1.3967x; 1.1757x over previous
#include <cuda_runtime.h>
#include <cuda_bf16.h>

// Problem dims (fixed by the reference)
#define BB   8
#define NN   1024
#define DD   256
#define HH   512
#define MMd  256
#define OOd  256
#define ROWS (BB*NN)          // 8192

// ---------------------------------------------------------------------------
// Scratch (device globals — allocation-free per harness rules)
// ---------------------------------------------------------------------------
__device__ float g_xproj[(size_t)ROWS * 4 * HH];       // 64 MB
__device__ float g_h    [(size_t)ROWS * HH];           // 16 MB
__device__ float g_scores[(size_t)BB * NN * NN];       // 32 MB (w in-place)
__device__ float g_sagg [(size_t)ROWS * HH];           // 16 MB
__device__ float g_t1   [(size_t)2 * ROWS * MMd];      // 16 MB (batched hidden)
__device__ float g_axav [(size_t)2 * ROWS * MMd];      // 16 MB (ax | av)
__device__ float g_agg  [(size_t)ROWS * OOd];          // 8 MB
__device__ float g_wp1  [(size_t)2 * MMd * HH];        // packed gx_W1|gv_W1
__device__ float g_wp2  [(size_t)2 * MMd * MMd];       // packed gx_W2|gv_W2
__device__ float g_bp1  [2 * MMd];
__device__ float g_bp2  [2 * MMd];
__device__ float g_rmask[ROWS];
__device__ unsigned g_cnt[NN];                         // per-timestep counters

__global__ void reset_cnt_kernel() {
    g_cnt[threadIdx.x] = 0u;
}

// ---------------------------------------------------------------------------
// Helpers
// ---------------------------------------------------------------------------
__device__ __forceinline__ void ffma2(unsigned long long& d,
                                      unsigned long long a, unsigned long long b) {
    asm("fma.rn.f32x2 %0, %1, %2, %3;" : "=l"(d) : "l"(a), "l"(b), "l"(d));
}
__device__ __forceinline__ float2 up2(unsigned long long p) {
    unsigned lo, hi;
    asm("mov.b64 {%0, %1}, %2;" : "=r"(lo), "=r"(hi) : "l"(p));
    return make_float2(__uint_as_float(lo), __uint_as_float(hi));
}
__device__ __forceinline__ float to_tf32(float x) {
    unsigned u;
    asm("cvt.rna.tf32.f32 %0, %1;" : "=r"(u) : "f"(x));
    return __uint_as_float(u);
}
__device__ __forceinline__ float tanh_ap(float x) {
    float y;
    asm("tanh.approx.f32 %0, %1;" : "=f"(y) : "f"(x));
    return y;
}
__device__ __forceinline__ void mma_tf32(float* c, const unsigned* a, const unsigned* b) {
    asm volatile(
        "mma.sync.aligned.m16n8k8.row.col.f32.tf32.tf32.f32 "
        "{%0,%1,%2,%3}, {%4,%5,%6,%7}, {%8,%9}, {%0,%1,%2,%3};"
        : "+f"(c[0]), "+f"(c[1]), "+f"(c[2]), "+f"(c[3])
        : "r"(a[0]), "r"(a[1]), "r"(a[2]), "r"(a[3]), "r"(b[0]), "r"(b[1]));
}

// ---------------------------------------------------------------------------
// Generic tf32 tensor-core GEMM:  C = epilogue( A @ B(^T) + bias )
// Tile 128x128x16, 256 threads (8 warps in 4x2 grid), warp tile 32x64,
// mma.sync m16n8k8 (2 m-subtiles x 8 n-subtiles x 2 k-steps per 16-k tile).
// fp32->tf32 conversion happens once, at STS time.
// Smem row stride 136 -> both fragment-load patterns are bank-conflict-free.
//   TRANSB=true : B is W [N,K] row-major; TRANSB=false: B is [K,N] row-major.
// ---------------------------------------------------------------------------
template<bool TRANSB, bool RELU, bool ACCUM, bool RMASK>
__global__ void __launch_bounds__(256, 2) gemm_k(
    const float* __restrict__ A, const float* __restrict__ B,
    const float* __restrict__ bias, const float* __restrict__ rmask,
    float* __restrict__ C,
    int K, int lda, int ldb, int ldc,
    long long sA, long long sB, long long sC, long long sBias)
{
    __shared__ __align__(16) float As[16][136];   // [k][m], tf32 values
    __shared__ __align__(16) float Bs[16][136];   // [k][n], tf32 values

    const int bz = blockIdx.z;
    A += (long long)bz * sA;
    B += (long long)bz * sB;
    C += (long long)bz * sC;
    if (bias) bias += (long long)bz * sBias;

    const int m0 = blockIdx.y * 128;
    const int n0 = blockIdx.x * 128;
    const int tid = threadIdx.x;
    const int lane = tid & 31;
    const int wid  = tid >> 5;
    const int warp_m = (wid & 3) * 32;   // 4 warps along M
    const int warp_n = (wid >> 2) * 64;  // 2 warps along N

    float acc[2][8][4];
#pragma unroll
    for (int mt = 0; mt < 2; mt++)
#pragma unroll
        for (int nt = 0; nt < 8; nt++)
#pragma unroll
            for (int i = 0; i < 4; i++) acc[mt][nt][i] = 0.f;

    for (int k0 = 0; k0 < K; k0 += 16) {
        // ---- load A tile (transpose into As[k][m], convert to tf32) ----
#pragma unroll
        for (int ii = 0; ii < 2; ii++) {
            int f   = tid + ii * 256;
            int row = f >> 2;
            int cg  = (f & 3) << 2;
            float4 v = *(const float4*)(A + (long long)(m0 + row) * lda + k0 + cg);
            As[cg + 0][row] = to_tf32(v.x);
            As[cg + 1][row] = to_tf32(v.y);
            As[cg + 2][row] = to_tf32(v.z);
            As[cg + 3][row] = to_tf32(v.w);
        }
        // ---- load B tile into Bs[k][n], convert to tf32 ----
        if (TRANSB) {
#pragma unroll
            for (int ii = 0; ii < 2; ii++) {
                int f   = tid + ii * 256;
                int row = f >> 2;              // n index
                int cg  = (f & 3) << 2;        // k index
                float4 v = *(const float4*)(B + (long long)(n0 + row) * ldb + k0 + cg);
                Bs[cg + 0][row] = to_tf32(v.x);
                Bs[cg + 1][row] = to_tf32(v.y);
                Bs[cg + 2][row] = to_tf32(v.z);
                Bs[cg + 3][row] = to_tf32(v.w);
            }
        } else {
#pragma unroll
            for (int ii = 0; ii < 2; ii++) {
                int f  = tid + ii * 256;
                int kr = f >> 5;
                int nc = (f & 31) << 2;
                float4 v = *(const float4*)(B + (long long)(k0 + kr) * ldb + n0 + nc);
                v.x = to_tf32(v.x); v.y = to_tf32(v.y);
                v.z = to_tf32(v.z); v.w = to_tf32(v.w);
                *(float4*)&Bs[kr][nc] = v;
            }
        }
        __syncthreads();

        // ---- mma microkernel: 2 k8 steps ----
#pragma unroll
        for (int ks = 0; ks < 16; ks += 8) {
            const int kc  = ks + (lane & 3);
            const int rr  = warp_m + (lane >> 2);
            const int ncb = warp_n + (lane >> 2);
            unsigned a[2][4], b[8][2];
#pragma unroll
            for (int mt = 0; mt < 2; mt++) {
                a[mt][0] = __float_as_uint(As[kc    ][rr + mt * 16]);
                a[mt][1] = __float_as_uint(As[kc    ][rr + mt * 16 + 8]);
                a[mt][2] = __float_as_uint(As[kc + 4][rr + mt * 16]);
                a[mt][3] = __float_as_uint(As[kc + 4][rr + mt * 16 + 8]);
            }
#pragma unroll
            for (int nt = 0; nt < 8; nt++) {
                b[nt][0] = __float_as_uint(Bs[kc    ][ncb + nt * 8]);
                b[nt][1] = __float_as_uint(Bs[kc + 4][ncb + nt * 8]);
            }
#pragma unroll
            for (int mt = 0; mt < 2; mt++)
#pragma unroll
                for (int nt = 0; nt < 8; nt++)
                    mma_tf32(acc[mt][nt], a[mt], b[nt]);
        }
        __syncthreads();
    }

    // ---- epilogue ----
#pragma unroll
    for (int mt = 0; mt < 2; mt++) {
        int r  = m0 + warp_m + mt * 16 + (lane >> 2);
        int r2 = r + 8;
        float rm1 = 1.f, rm2 = 1.f;
        if (RMASK) { rm1 = rmask[r]; rm2 = rmask[r2]; }
#pragma unroll
        for (int nt = 0; nt < 8; nt++) {
            int col = n0 + warp_n + nt * 8 + 2 * (lane & 3);
            float2 v1 = make_float2(acc[mt][nt][0], acc[mt][nt][1]);
            float2 v2 = make_float2(acc[mt][nt][2], acc[mt][nt][3]);
            if (bias) {
                float2 bb = *(const float2*)(bias + col);
                v1.x += bb.x; v1.y += bb.y;
                v2.x += bb.x; v2.y += bb.y;
            }
            float2* cp1 = (float2*)(C + (long long)r  * ldc + col);
            float2* cp2 = (float2*)(C + (long long)r2 * ldc + col);
            if (ACCUM) {
                float2 o1 = *cp1, o2 = *cp2;
                v1.x += o1.x; v1.y += o1.y;
                v2.x += o2.x; v2.y += o2.y;
            }
            if (RELU) {
                v1.x = fmaxf(v1.x, 0.f); v1.y = fmaxf(v1.y, 0.f);
                v2.x = fmaxf(v2.x, 0.f); v2.y = fmaxf(v2.y, 0.f);
            }
            if (RMASK) { v1.x *= rm1; v1.y *= rm1; v2.x *= rm2; v2.y *= rm2; }
            *cp1 = v1;
            *cp2 = v2;
        }
    }
}

// ---------------------------------------------------------------------------
// Persistent LSTM kernel: 128 CTAs x 256 threads (structure proven in R13).
// Warp (u, bg) owns the 4 gate rows of hidden unit j0+u for batches bg*4..+3;
// full butterfly reduce; in-warp cell update on lanes 0-3 with tanh.approx.
// Cross-CTA sync: per-step counter; tid0 ld.acquire poll / red.release.
// ---------------------------------------------------------------------------
#define LSTM_CTAS 128

__global__ void __launch_bounds__(256) lstm_kernel(
    const float* __restrict__ xproj,   // [8192, 2048] (no bias)
    const float* __restrict__ W_hh,    // [2048, 512]
    const float* __restrict__ b_ih,    // [2048]
    const float* __restrict__ b_hh,    // [2048]
    float* __restrict__ h_out)         // [8192, 512], row = b*1024 + t
{
    __shared__ __align__(16) float hsm[8 * 512];

    const int tid  = threadIdx.x;
    const int cta  = blockIdx.x;
    const int j0   = cta * 4;
    const int w    = tid >> 5;
    const int lane = tid & 31;
    const int u    = w >> 1;           // hidden unit j0+u
    const int bg   = w & 1;            // batch group: batches bg*4 .. bg*4+3

    // W_hh rows q*512 + j0 + u (q = gate i,f,g,o) into registers, FFMA2-paired
    ulonglong2 wq[4][4];
    float bq[4];
#pragma unroll
    for (int q = 0; q < 4; q++) {
        int r = q * 512 + j0 + u;
        const float* src = W_hh + (long long)r * 512;
#pragma unroll
        for (int i = 0; i < 4; i++)
            wq[q][i] = *(const ulonglong2*)&src[lane * 4 + i * 128];
        bq[q] = b_ih[r] + b_hh[r];
    }
    float c = 0.f;                     // valid on lanes 0-3: batch bg*4+lane

    for (int idx = tid; idx < 8 * 512; idx += 256) hsm[idx] = 0.f;  // h(-1)=0
    __syncthreads();

    const float* Hbase = &hsm[bg * 4 * 512];

    for (int t = 0; t < 1024; t++) {
        // Prefetch x-projection for the update lanes (overlaps the wait)
        float xp[4] = {0.f, 0.f, 0.f, 0.f};
        if (lane < 4) {
            int batch = bg * 4 + lane;
            long long base = (long long)(batch * 1024 + t) * 2048 + j0 + u;
#pragma unroll
            for (int q = 0; q < 4; q++)
                xp[q] = __ldg(&xproj[base + q * 512]);
        }
        if (t > 0) {
            // Wait for h(t-1) from all CTAs (tid0 polls; pairs with release)
            if (tid == 0) {
                const unsigned* cp = &g_cnt[t - 1];
                unsigned v;
                do {
                    asm volatile("ld.acquire.gpu.u32 %0, [%1];"
                                 : "=r"(v) : "l"(cp) : "memory");
                } while (v < (unsigned)LSTM_CTAS);
            }
            __syncthreads();
            // Stage h(t-1) into SMEM
#pragma unroll
            for (int ii = 0; ii < 4; ii++) {
                int f  = tid + ii * 256;
                int b  = f >> 7;
                int kk = (f & 127) * 4;
                *(float4*)&hsm[b * 512 + kk] =
                    *(const float4*)&h_out[(long long)(b * 1024 + t - 1) * 512 + kk];
            }
            __syncthreads();
        }

        // gates(q, b) = sum_k W[q*512+j0+u][k] * h[b][k]
        unsigned long long acc[4][4];
#pragma unroll
        for (int q = 0; q < 4; q++)
#pragma unroll
            for (int bb = 0; bb < 4; bb++) acc[q][bb] = 0ull;

#pragma unroll
        for (int i = 0; i < 4; i++) {
            int kk = lane * 4 + i * 128;
            ulonglong2 hq[4];
#pragma unroll
            for (int bb = 0; bb < 4; bb++)
                hq[bb] = *(const ulonglong2*)&Hbase[bb * 512 + kk];
#pragma unroll
            for (int q = 0; q < 4; q++)
#pragma unroll
                for (int bb = 0; bb < 4; bb++) {
                    ffma2(acc[q][bb], wq[q][i].x, hq[bb].x);
                    ffma2(acc[q][bb], wq[q][i].y, hq[bb].y);
                }
        }

        float val[4][4];
#pragma unroll
        for (int q = 0; q < 4; q++)
#pragma unroll
            for (int bb = 0; bb < 4; bb++) {
                float2 p = up2(acc[q][bb]);
                val[q][bb] = p.x + p.y;
            }
#pragma unroll
        for (int off = 16; off > 0; off >>= 1)
#pragma unroll
            for (int q = 0; q < 4; q++)
#pragma unroll
                for (int bb = 0; bb < 4; bb++)
                    val[q][bb] += __shfl_xor_sync(0xffffffffu, val[q][bb], off);

        // In-warp cell update: lane bb handles batch bg*4+bb of unit j0+u
        if (lane < 4) {
            int batch = bg * 4 + lane;
            float gi = val[0][lane] + xp[0] + bq[0];
            float gf = val[1][lane] + xp[1] + bq[1];
            float gg = val[2][lane] + xp[2] + bq[2];
            float go = val[3][lane] + xp[3] + bq[3];
            float si = 0.5f * tanh_ap(0.5f * gi) + 0.5f;
            float sf = 0.5f * tanh_ap(0.5f * gf) + 0.5f;
            float so = 0.5f * tanh_ap(0.5f * go) + 0.5f;
            float tg = tanh_ap(gg);
            c = sf * c + si * tg;
            float tc = tanh_ap(c);
            h_out[(long long)(batch * 1024 + t) * 512 + j0 + u] = so * tc;
        }
        __syncthreads();   // HB: all warps' h stores -> tid0's release

        if (tid == 0) {
            const unsigned* cp = &g_cnt[t];
            asm volatile("red.release.gpu.add.u32 [%0], %1;"
                         :: "l"(cp), "r"(1u) : "memory");
        }
    }
}

// ---------------------------------------------------------------------------
// Masked softmax over scores rows; writes w in-place and the has-neighbor mask
// ---------------------------------------------------------------------------
__global__ void __launch_bounds__(256) softmax_kernel(
    float* __restrict__ scores, const int* __restrict__ adj,
    float* __restrict__ rmask)
{
    const int r = blockIdx.x;              // 0..8191 == (b*1024 + i)
    const int i = r & (NN - 1);
    float* srow      = scores + (long long)r * NN;
    const int* arow  = adj    + (long long)r * NN;
    const int tid  = threadIdx.x;
    const int lane = tid & 31, wid = tid >> 5;

    float s[4]; int m[4];
    float mx = -1e30f;
    int cnt = 0;
#pragma unroll
    for (int u = 0; u < 4; u++) {
        int j = tid + u * 256;
        float v  = srow[j];
        int   mk = (arow[j] > 0) && (j != i);
        s[u] = v; m[u] = mk;
        if (mk) { mx = fmaxf(mx, v); cnt++; }
    }

    __shared__ float rf[8];
    __shared__ int   ri[8];
    __shared__ float s_mx, s_inv;
    __shared__ int   s_cnt;

#pragma unroll
    for (int off = 16; off; off >>= 1) {
        mx   = fmaxf(mx, __shfl_xor_sync(0xffffffffu, mx, off));
        cnt += __shfl_xor_sync(0xffffffffu, cnt, off);
    }
    if (lane == 0) { rf[wid] = mx; ri[wid] = cnt; }
    __syncthreads();
    if (tid == 0) {
        float m2 = rf[0]; int c2 = ri[0];
        for (int k = 1; k < 8; k++) { m2 = fmaxf(m2, rf[k]); c2 += ri[k]; }
        s_mx = m2; s_cnt = c2;
    }
    __syncthreads();

    if (s_cnt == 0) {
#pragma unroll
        for (int u = 0; u < 4; u++) srow[tid + u * 256] = 0.f;
        if (tid == 0) rmask[r] = 0.f;
        return;
    }
    float mxAll = s_mx;
    float e[4];
    float sum = 0.f;
#pragma unroll
    for (int u = 0; u < 4; u++) {
        e[u] = m[u] ? expf(s[u] - mxAll) : 0.f;
        sum += e[u];
    }
#pragma unroll
    for (int off = 16; off; off >>= 1) sum += __shfl_xor_sync(0xffffffffu, sum, off);
    if (lane == 0) rf[wid] = sum;
    __syncthreads();
    if (tid == 0) {
        float tot = 0.f;
        for (int k = 0; k < 8; k++) tot += rf[k];
        s_inv = 1.f / tot;
    }
    __syncthreads();
    float inv = s_inv;
#pragma unroll
    for (int u = 0; u < 4; u++) srow[tid + u * 256] = e[u] * inv;
    if (tid == 0) rmask[r] = 1.f;
}

// ---------------------------------------------------------------------------
// Launch
// ---------------------------------------------------------------------------
extern "C" void kernel_launch(void* const* d_in, const int* in_sizes, int n_in,
                              void* d_out, int out_size)
{
    const float* feats = (const float*)d_in[0];
    const int*   adj   = (const int*)  d_in[1];
    const float* W_ih  = (const float*)d_in[2];
    const float* W_hh  = (const float*)d_in[3];
    const float* b_ih  = (const float*)d_in[4];
    const float* b_hh  = (const float*)d_in[5];
    const float* gx_W1 = (const float*)d_in[6];
    const float* gx_b1 = (const float*)d_in[7];
    const float* gx_W2 = (const float*)d_in[8];
    const float* gx_b2 = (const float*)d_in[9];
    const float* gz_W1 = (const float*)d_in[10];
    const float* gz_b1 = (const float*)d_in[11];
    const float* gz_W2 = (const float*)d_in[12];
    const float* gz_b2 = (const float*)d_in[13];
    const float* gv_W1 = (const float*)d_in[14];
    const float* gv_b1 = (const float*)d_in[15];
    const float* gv_W2 = (const float*)d_in[16];
    const float* gv_b2 = (const float*)d_in[17];
    const float* gn_W1 = (const float*)d_in[18];
    const float* gn_b1 = (const float*)d_in[19];
    const float* gn_W2 = (const float*)d_in[20];
    const float* gn_b2 = (const float*)d_in[21];
    const float* out_W = (const float*)d_in[22];
    const float* out_b = (const float*)d_in[23];
    float* out = (float*)d_out;

    float *xproj, *h, *scores, *sagg, *t1, *axav, *agg, *rmask;
    float *wp1, *wp2, *bp1, *bp2;
    cudaGetSymbolAddress((void**)&xproj,  g_xproj);
    cudaGetSymbolAddress((void**)&h,      g_h);
    cudaGetSymbolAddress((void**)&scores, g_scores);
    cudaGetSymbolAddress((void**)&sagg,   g_sagg);
    cudaGetSymbolAddress((void**)&t1,     g_t1);
    cudaGetSymbolAddress((void**)&axav,   g_axav);
    cudaGetSymbolAddress((void**)&agg,    g_agg);
    cudaGetSymbolAddress((void**)&rmask,  g_rmask);
    cudaGetSymbolAddress((void**)&wp1,    g_wp1);
    cudaGetSymbolAddress((void**)&wp2,    g_wp2);
    cudaGetSymbolAddress((void**)&bp1,    g_bp1);
    cudaGetSymbolAddress((void**)&bp2,    g_bp2);

    const long long PW1 = (long long)MMd * HH;    // 131072
    const long long PW2 = (long long)MMd * MMd;   // 65536
    const long long PT  = (long long)ROWS * MMd;  // 2097152
    float* ax = axav;
    float* av = axav + PT;

    // Pack gx|gv weights/biases for batched MLP GEMMs (tiny D2D copies)
    cudaMemcpyAsync(wp1,       gx_W1, PW1 * 4, cudaMemcpyDeviceToDevice);
    cudaMemcpyAsync(wp1 + PW1, gv_W1, PW1 * 4, cudaMemcpyDeviceToDevice);
    cudaMemcpyAsync(wp2,       gx_W2, PW2 * 4, cudaMemcpyDeviceToDevice);
    cudaMemcpyAsync(wp2 + PW2, gv_W2, PW2 * 4, cudaMemcpyDeviceToDevice);
    cudaMemcpyAsync(bp1,       gx_b1, MMd * 4, cudaMemcpyDeviceToDevice);
    cudaMemcpyAsync(bp1 + MMd, gv_b1, MMd * 4, cudaMemcpyDeviceToDevice);
    cudaMemcpyAsync(bp2,       gx_b2, MMd * 4, cudaMemcpyDeviceToDevice);
    cudaMemcpyAsync(bp2 + MMd, gv_b2, MMd * 4, cudaMemcpyDeviceToDevice);

    const dim3 blk(256);
    const dim3 gSmall(2, 64, 1);   // [8192 x 256] outputs

    // 1. xproj = feats @ W_ih^T            [8192,2048], K=256
    gemm_k<true,false,false,false><<<dim3(16, 64, 1), blk>>>(
        feats, W_ih, nullptr, nullptr, xproj, 256, 256, 256, 2048, 0, 0, 0, 0);

    // 2. LSTM recurrence -> h [8192,512]
    reset_cnt_kernel<<<1, NN>>>();
    lstm_kernel<<<LSTM_CTAS, 256>>>(xproj, W_hh, b_ih, b_hh, h);

    // 3+4. batched gx/gv MLPs
    gemm_k<true,true,false,false><<<dim3(2, 64, 2), blk>>>(
        h, wp1, bp1, nullptr, t1, 512, 512, 512, 256, 0, PW1, PT, MMd);
    gemm_k<true,false,false,false><<<dim3(2, 64, 2), blk>>>(
        t1, wp2, bp2, nullptr, axav, 256, 256, 256, 256, PT, PW2, PT, MMd);

    // 5. scores[b] = ax[b] @ av[b]^T       batched [1024,1024], K=256
    gemm_k<true,false,false,false><<<dim3(8, 8, 8), blk>>>(
        ax, av, nullptr, nullptr, scores, 256, 256, 256, 1024,
        (long long)1024 * 256, (long long)1024 * 256, (long long)1024 * 1024, 0);

    // 6. w = masked softmax(scores) (in place) + rmask
    softmax_kernel<<<ROWS, 256>>>(scores, adj, rmask);

    // 7. sagg[b] = w[b] @ h[b]             batched [1024,512], K=1024
    gemm_k<false,false,false,false><<<dim3(4, 8, 8), blk>>>(
        scores, h, nullptr, nullptr, sagg, 1024, 1024, 512, 512,
        (long long)1024 * 1024, (long long)1024 * 512, (long long)1024 * 512, 0);

    // 8. z = mlp_gz(sagg)
    gemm_k<true,true,false,false><<<gSmall, blk>>>(
        sagg, gz_W1, gz_b1, nullptr, t1, 512, 512, 512, 256, 0, 0, 0, 0);
    gemm_k<true,false,false,false><<<gSmall, blk>>>(
        t1, gz_W2, gz_b2, nullptr, axav, 256, 256, 256, 256, 0, 0, 0, 0);

    // 9. agg = mlp_gn(z) * has_nb
    gemm_k<true,true,false,false><<<gSmall, blk>>>(
        axav, gn_W1, gn_b1, nullptr, t1, 256, 256, 256, 256, 0, 0, 0, 0);
    gemm_k<true,false,false,true><<<gSmall, blk>>>(
        t1, gn_W2, gn_b2, rmask, agg, 256, 256, 256, 256, 0, 0, 0, 0);

    // 10. out = h @ out_W[:, :512]^T + out_b ;  out += agg @ out_W[:, 512:]^T
    gemm_k<true,false,false,false><<<gSmall, blk>>>(
        h, out_W, out_b, nullptr, out, 512, 512, 768, 256, 0, 0, 0, 0);
    gemm_k<true,false,true,false><<<gSmall, blk>>>(
        agg, out_W + 512, nullptr, nullptr, out, 256, 256, 768, 256, 0, 0, 0, 0);
}